// round 3
// baseline (speedup 1.0000x reference)
#include <cuda_runtime.h>

// Problem constants (static per reference)
#define NGR 4
#define GF 256
#define DIN 834
#define SS 1568
#define NB 16
#define TOT 160
#define IDIM 1024
#define NMAX 16

// ---------------- scratch (static device globals; no runtime allocs) -------
__device__ float g_emb[TOT * NGR * GF];            // [t][g][f]
__device__ float g_ctx[NB * NGR * GF * SS];        // [b][g][f][s]  ~103MB
__device__ float g_adj[NB * NGR * NMAX * SS];      // [b][g][n][s]
__device__ float g_flat[TOT * NGR * GF];           // [t][g][f]
__device__ int   g_off[NB];
__device__ int   g_cnt[NB];

// ---------------- f32x2 helpers ---------------------------------------------
__device__ __forceinline__ void ffma2(unsigned long long& d,
                                      unsigned long long a,
                                      unsigned long long b) {
    asm("fma.rn.f32x2 %0, %1, %2, %0;" : "+l"(d) : "l"(a), "l"(b));
}
__device__ __forceinline__ void unpack2(float& lo, float& hi, unsigned long long v) {
    asm("mov.b64 {%0, %1}, %2;" : "=f"(lo), "=f"(hi) : "l"(v));
}

// ---------------- K0: ragged bookkeeping, dtype-autodetecting --------------
__global__ void init_offsets_k(const void* __restrict__ counts) {
    if (threadIdx.x == 0 && blockIdx.x == 0) {
        const int* c32 = (const int*)counts;
        const long long* c64 = (const long long*)counts;
        long long s = 0;
        bool ok32 = true;
        for (int b = 0; b < NB; b++) {
            int v = c32[b];
            if (v < 0 || v > NMAX) ok32 = false;
            s += v;
        }
        if (s != TOT) ok32 = false;
        int acc = 0;
        for (int b = 0; b < NB; b++) {
            int c = ok32 ? c32[b] : (int)c64[b];
            if (c < 0) c = 0;
            if (c > NMAX) c = NMAX;
            g_off[b] = acc;
            g_cnt[b] = c;
            acc += c;
        }
    }
}

// ---------------- generic GEMM: C[M][N] = A[M][K] * B[N][K]^T (+bias,+relu) -
__global__ void __launch_bounds__(256) gemm_nt_k(
    const float* __restrict__ A, int lda, long long aZ,
    const float* __restrict__ Bm, int ldb, long long bZ,
    const float* __restrict__ bias,
    float* __restrict__ C, int ldc, long long cZ,
    int K, int doRelu)
{
    int z = blockIdx.z;
    A  += (long long)z * aZ;
    Bm += (long long)z * bZ;
    C  += (long long)z * cZ;

    __shared__ __align__(16) float As[32][33];   // [k][m]
    __shared__ __align__(16) float Bs[32][65];   // [k][n]

    int tid = threadIdx.x;
    int m0 = blockIdx.x * 32;
    int n0 = blockIdx.y * 64;
    int tx = tid % 64;
    int ty = tid / 64;

    float acc[8];
#pragma unroll
    for (int i = 0; i < 8; i++) acc[i] = 0.f;

    for (int k0 = 0; k0 < K; k0 += 32) {
#pragma unroll
        for (int t = 0; t < 4; t++) {
            int lin = tid + 256 * t;
            int k = lin & 31, m = lin >> 5;
            As[k][m] = A[(m0 + m) * (long long)lda + k0 + k];
        }
#pragma unroll
        for (int t = 0; t < 8; t++) {
            int lin = tid + 256 * t;
            int k = lin & 31, n = lin >> 5;
            Bs[k][n] = Bm[(n0 + n) * (long long)ldb + k0 + k];
        }
        __syncthreads();
#pragma unroll
        for (int k = 0; k < 32; k++) {
            float bv = Bs[k][tx];
#pragma unroll
            for (int i = 0; i < 8; i++)
                acc[i] += As[k][ty + 4 * i] * bv;
        }
        __syncthreads();
    }

    float bb = bias ? bias[n0 + tx] : 0.f;
#pragma unroll
    for (int i = 0; i < 8; i++) {
        int m = m0 + ty + 4 * i;
        float v = acc[i] + bb;
        if (doRelu) v = fmaxf(v, 0.f);
        C[m * (long long)ldc + n0 + tx] = v;
    }
}

// ---------------- K2: ctx[b,g,f,s] = sum_c W_c[g,f,c]*fm[b,c,s] + b_c[g,f] --
// 128x128x8 SGEMM with packed FFMA2 (f32x2), A pre-duplicated in smem.
// 8x8 per thread = 8x(4 pairs), grid (13, 2, 64)
__global__ void __launch_bounds__(256) ctx_gemm_k(
    const float* __restrict__ Wc, const float* __restrict__ fm,
    const float* __restrict__ bc)
{
    int z = blockIdx.z;
    int b = z >> 2, g = z & 3;
    const float* A = Wc + (long long)g * GF * DIN;     // [256][834]
    const float* B = fm + (long long)b * DIN * SS;     // [834][1568]
    float* C = g_ctx + (long long)z * GF * SS;
    const float* bias = bc + g * GF;

    __shared__ __align__(16) float AsD[8][256];  // [k][2m] duplicated pairs
    __shared__ __align__(16) float Bs[8][128];   // [k][n]

    int tid = threadIdx.x;
    int m0 = blockIdx.y * 128;
    int n0 = blockIdx.x * 128;
    int tx = tid % 16, ty = tid / 16;

    unsigned long long acc2[8][4];
#pragma unroll
    for (int i = 0; i < 8; i++)
#pragma unroll
        for (int j = 0; j < 4; j++) acc2[i][j] = 0ull;

    for (int k0 = 0; k0 < DIN; k0 += 8) {
        // A tile: 128m x 8k, stored duplicated: AsD[k][2m]=AsD[k][2m+1]=v
#pragma unroll
        for (int t = 0; t < 4; t++) {
            int lin = tid + 256 * t;
            int m = lin & 127, k = lin >> 7;
            float v = 0.f;
            if (k0 + k < DIN) v = A[(m0 + m) * DIN + k0 + k];
            AsD[k][2 * m]     = v;
            AsD[k][2 * m + 1] = v;
        }
        // B tile: 8k x 128n
#pragma unroll
        for (int t = 0; t < 4; t++) {
            int lin = tid + 256 * t;
            int n = lin & 127, k = lin >> 7;
            float v = 0.f;
            if (k0 + k < DIN && n0 + n < SS) v = B[(k0 + k) * SS + n0 + n];
            Bs[k][n] = v;
        }
        __syncthreads();
#pragma unroll
        for (int k = 0; k < 8; k++) {
            // a-dup pairs: 4 x 16B loads -> {a_i,a_i} as u64 each
            ulonglong2 aq0 = *(const ulonglong2*)&AsD[k][ty * 16 + 0];
            ulonglong2 aq1 = *(const ulonglong2*)&AsD[k][ty * 16 + 4];
            ulonglong2 aq2 = *(const ulonglong2*)&AsD[k][ty * 16 + 8];
            ulonglong2 aq3 = *(const ulonglong2*)&AsD[k][ty * 16 + 12];
            // b pairs: natural from contiguous layout
            ulonglong2 bq0 = *(const ulonglong2*)&Bs[k][tx * 8];
            ulonglong2 bq1 = *(const ulonglong2*)&Bs[k][tx * 8 + 4];
            unsigned long long ad[8] = {aq0.x, aq0.y, aq1.x, aq1.y,
                                        aq2.x, aq2.y, aq3.x, aq3.y};
            unsigned long long bp[4] = {bq0.x, bq0.y, bq1.x, bq1.y};
#pragma unroll
            for (int i = 0; i < 8; i++)
#pragma unroll
                for (int j = 0; j < 4; j++)
                    ffma2(acc2[i][j], ad[i], bp[j]);
        }
        __syncthreads();
    }

#pragma unroll
    for (int i = 0; i < 8; i++) {
        int m = m0 + ty * 8 + i;
        float bb = bias[m];
#pragma unroll
        for (int j = 0; j < 4; j++) {
            float lo, hi;
            unpack2(lo, hi, acc2[i][j]);
            int n = n0 + tx * 8 + 2 * j;
            if (n < SS)     C[m * SS + n]     = lo + bb;
            if (n + 1 < SS) C[m * SS + n + 1] = hi + bb;
        }
    }
}

// ---------------- K3: adj[b,g,n,s] = sum_f emb_pad[b,n,g,f]*ctx[b,g,f,s] ----
__global__ void __launch_bounds__(256) adj_logits_k() {
    int g = blockIdx.y, b = blockIdx.z;
    __shared__ __align__(16) float a_s[GF * NMAX];   // [f][n]
    int tid = threadIdx.x;
    int cnt = g_cnt[b], off = g_off[b];

    for (int idx = tid; idx < GF * NMAX; idx += 256) {
        int n = idx >> 8, f = idx & 255;
        float v = 0.f;
        if (n < cnt) v = g_emb[(off + n) * (NGR * GF) + g * GF + f];
        a_s[f * NMAX + n] = v;
    }
    __syncthreads();

    int s = blockIdx.x * 256 + tid;
    if (s >= SS) return;

    const float* ctxp = g_ctx + ((long long)(b * NGR + g)) * GF * SS + s;
    float acc[NMAX];
#pragma unroll
    for (int n = 0; n < NMAX; n++) acc[n] = 0.f;

    const float4* ap = (const float4*)a_s;
#pragma unroll 4
    for (int f = 0; f < GF; f++) {
        float v = ctxp[f * SS];
        float4 a0 = ap[f * 4 + 0];
        float4 a1 = ap[f * 4 + 1];
        float4 a2 = ap[f * 4 + 2];
        float4 a3 = ap[f * 4 + 3];
        acc[0]  += v * a0.x;  acc[1]  += v * a0.y;  acc[2]  += v * a0.z;  acc[3]  += v * a0.w;
        acc[4]  += v * a1.x;  acc[5]  += v * a1.y;  acc[6]  += v * a1.z;  acc[7]  += v * a1.w;
        acc[8]  += v * a2.x;  acc[9]  += v * a2.y;  acc[10] += v * a2.z;  acc[11] += v * a2.w;
        acc[12] += v * a3.x;  acc[13] += v * a3.y;  acc[14] += v * a3.z;  acc[15] += v * a3.w;
    }

    float* adjp = g_adj + ((long long)(b * NGR + g)) * NMAX * SS + s;
#pragma unroll
    for (int n = 0; n < NMAX; n++) adjp[n * SS] = acc[n];
}

// ---------------- K4: softmax over s per valid (b,g,n) row ------------------
__global__ void __launch_bounds__(256) softmax_k() {
    int n = blockIdx.x, g = blockIdx.y, b = blockIdx.z;
    if (n >= g_cnt[b]) return;
    float* row = g_adj + ((long long)((b * NGR + g) * NMAX + n)) * SS;
    int tid = threadIdx.x;
    __shared__ float red[8];

    float mx = -1e30f;
    for (int s = tid; s < SS; s += 256) mx = fmaxf(mx, row[s]);
#pragma unroll
    for (int o = 16; o > 0; o >>= 1) mx = fmaxf(mx, __shfl_xor_sync(0xffffffffu, mx, o));
    if ((tid & 31) == 0) red[tid >> 5] = mx;
    __syncthreads();
    if (tid < 32) {
        float v = (tid < 8) ? red[tid] : -1e30f;
#pragma unroll
        for (int o = 4; o > 0; o >>= 1) v = fmaxf(v, __shfl_xor_sync(0xffffffffu, v, o));
        if (tid == 0) red[0] = v;
    }
    __syncthreads();
    mx = red[0];
    __syncthreads();

    float sum = 0.f;
    for (int s = tid; s < SS; s += 256) {
        float e = __expf(row[s] - mx);
        row[s] = e;
        sum += e;
    }
#pragma unroll
    for (int o = 16; o > 0; o >>= 1) sum += __shfl_xor_sync(0xffffffffu, sum, o);
    if ((tid & 31) == 0) red[tid >> 5] = sum;
    __syncthreads();
    if (tid < 32) {
        float v = (tid < 8) ? red[tid] : 0.f;
#pragma unroll
        for (int o = 4; o > 0; o >>= 1) v += __shfl_xor_sync(0xffffffffu, v, o);
        if (tid == 0) red[0] = v;
    }
    __syncthreads();
    float inv = 1.f / red[0];
    for (int s = tid; s < SS; s += 256) row[s] *= inv;
}

// ---------------- K5: flat[t,g,f] = sum_s adj[b,g,n,s]*ctx[b,g,f,s] + emb ---
__global__ void __launch_bounds__(256) aggregate_k() {
    int z = blockIdx.y;
    int b = z >> 2, g = z & 3;
    int f0 = blockIdx.x * 64;

    __shared__ __align__(16) float adjS[NMAX][33];
    __shared__ __align__(16) float ctxS[32][65];

    const float* adjp = g_adj + (long long)z * NMAX * SS;
    const float* ctxp = g_ctx + (long long)z * GF * SS;

    int tid = threadIdx.x;
    int fid = tid % 64, grp = tid / 64;
    float acc[4] = {0.f, 0.f, 0.f, 0.f};

    for (int s0 = 0; s0 < SS; s0 += 32) {
#pragma unroll
        for (int t = 0; t < 2; t++) {
            int lin = tid + 256 * t;
            int k = lin & 31, n = lin >> 5;
            adjS[n][k] = adjp[n * SS + s0 + k];
        }
#pragma unroll
        for (int t = 0; t < 8; t++) {
            int lin = tid + 256 * t;
            int k = lin & 31, i = lin >> 5;
            ctxS[k][i] = ctxp[(f0 + i) * SS + s0 + k];
        }
        __syncthreads();
#pragma unroll
        for (int k = 0; k < 32; k++) {
            float bv = ctxS[k][fid];
#pragma unroll
            for (int j = 0; j < 4; j++)
                acc[j] += adjS[grp * 4 + j][k] * bv;
        }
        __syncthreads();
    }

    int cnt = g_cnt[b], off = g_off[b];
#pragma unroll
    for (int j = 0; j < 4; j++) {
        int n = grp * 4 + j;
        if (n < cnt) {
            long long idx = (long long)(off + n) * (NGR * GF) + g * GF + f0 + fid;
            g_flat[idx] = acc[j] + g_emb[idx];
        }
    }
}

// ---------------- launch ----------------------------------------------------
extern "C" void kernel_launch(void* const* d_in, const int* in_sizes, int n_in,
                              void* d_out, int out_size) {
    const float* actor = (const float*)d_in[0];
    const float* fmap  = (const float*)d_in[1];
    const float* W_a   = (const float*)d_in[2];
    const float* b_a   = (const float*)d_in[3];
    const float* W_c   = (const float*)d_in[4];
    const float* b_c   = (const float*)d_in[5];
    const float* W_h   = (const float*)d_in[6];
    const void*  counts = d_in[7];
    int nbias = 0;
    for (int i = 0; i < n_in; i++) {
        switch (in_sizes[i]) {
            case TOT * IDIM:      actor = (const float*)d_in[i]; break;
            case NB * DIN * SS:   fmap  = (const float*)d_in[i]; break;
            case NGR * GF * IDIM: W_a   = (const float*)d_in[i]; break;
            case NGR * GF * DIN:  W_c   = (const float*)d_in[i]; break;
            case NGR * GF * GF:   W_h   = (const float*)d_in[i]; break;
            case NGR * GF:
                if (nbias++ == 0) b_a = (const float*)d_in[i];
                else              b_c = (const float*)d_in[i];
                break;
            case NB:              counts = d_in[i]; break;
            default: break;
        }
    }
    float* out = (float*)d_out;                   // [160, 1024]

    float *emb_p, *flat_p;
    cudaGetSymbolAddress((void**)&emb_p, g_emb);
    cudaGetSymbolAddress((void**)&flat_p, g_flat);

    init_offsets_k<<<1, 32>>>(counts);

    // K1: emb (M=160, N=1024, K=1024)
    gemm_nt_k<<<dim3(5, 16, 1), 256>>>(actor, IDIM, 0,
                                       W_a, IDIM, 0,
                                       b_a,
                                       emb_p, NGR * GF, 0,
                                       IDIM, 0);

    // K2: ctx (dominant GEMM, FFMA2)
    ctx_gemm_k<<<dim3(13, 2, 64), 256>>>(W_c, fmap, b_c);

    // K3: adjacency logits
    adj_logits_k<<<dim3(7, NGR, NB), 256>>>();

    // K4: softmax over context locations
    softmax_k<<<dim3(NMAX, NGR, NB), 256>>>();

    // K5: aggregate + residual, scatter to ragged flat
    aggregate_k<<<dim3(4, 64), 256>>>();

    // K6: head linear + relu (per-g GEMM, M=160, N=256, K=256)
    gemm_nt_k<<<dim3(5, 4, 4), 256>>>(flat_p, NGR * GF, GF,
                                      W_h, GF, (long long)GF * GF,
                                      nullptr,
                                      out, NGR * GF, GF,
                                      GF, 1);
}

// round 5
// speedup vs baseline: 2.0920x; 2.0920x over previous
#include <cuda_runtime.h>
#include <cuda_bf16.h>
#include <cstdint>

// Problem constants
#define NGR 4
#define GF 256
#define DIN 834
#define SS 1568
#define NB 16
#define TOT 160
#define IDIM 1024
#define NMAX 16

// padded dims for MMA
#define CPAD 896            // K padded (28 chunks of 32)
#define SPAD 1664           // s padded (13 tiles of 128)
#define KCHUNKS 28
#define STILES 13
#define MTILES 2            // 256 f / 128

// smem layout for ctx_mma_k: 80B row stride, 128 rows per tile
#define RS 80
#define TILE_B (128 * RS)   // 10240
#define AH_OFF 0
#define AL_OFF (TILE_B)
#define BH_OFF (2 * TILE_B)
#define BL_OFF (3 * TILE_B)
#define STAGE_B (4 * TILE_B)        // 40960
#define SMEM_DYN (2 * STAGE_B)      // 81920

// ---------------- scratch (static device globals) --------------------------
__device__ float g_emb[TOT * NGR * GF];
__device__ float g_ctx[NB * NGR * GF * SS];        // [z][f][s]
__device__ float g_adj[NB * NGR * NMAX * SS];
__device__ float g_flat[TOT * NGR * GF];
__device__ int   g_off[NB];
__device__ int   g_cnt[NB];
__device__ __nv_bfloat16 g_fmT_hi[(long long)NB * SPAD * CPAD];  // [b][s][c]
__device__ __nv_bfloat16 g_fmT_lo[(long long)NB * SPAD * CPAD];
__device__ __nv_bfloat16 g_w_hi[NGR * GF * CPAD];                // [g][f][c]
__device__ __nv_bfloat16 g_w_lo[NGR * GF * CPAD];

// ---------------- PTX helpers (baseline ISA only) ---------------------------
__device__ __forceinline__ uint32_t smem_u32(const void* p) {
    uint32_t a;
    asm("{ .reg .u64 t; cvta.to.shared.u64 t, %1; cvt.u32.u64 %0, t; }"
        : "=r"(a) : "l"(p));
    return a;
}
__device__ __forceinline__ void cp16(uint32_t dst, const void* src) {
    asm volatile("cp.async.cg.shared.global [%0], [%1], 16;"
                 :: "r"(dst), "l"(src) : "memory");
}
__device__ __forceinline__ void cp_commit() {
    asm volatile("cp.async.commit_group;" ::: "memory");
}
template <int N>
__device__ __forceinline__ void cp_wait() {
    asm volatile("cp.async.wait_group %0;" :: "n"(N) : "memory");
}
__device__ __forceinline__ void ldsm4(uint32_t& r0, uint32_t& r1, uint32_t& r2,
                                      uint32_t& r3, uint32_t a) {
    asm volatile("ldmatrix.sync.aligned.m8n8.x4.shared.b16 {%0,%1,%2,%3}, [%4];"
                 : "=r"(r0), "=r"(r1), "=r"(r2), "=r"(r3) : "r"(a));
}
__device__ __forceinline__ void mma_bf16(float* c, const uint32_t* a,
                                         const uint32_t* b) {
    asm volatile(
        "mma.sync.aligned.m16n8k16.row.col.f32.bf16.bf16.f32 "
        "{%0,%1,%2,%3}, {%4,%5,%6,%7}, {%8,%9}, {%0,%1,%2,%3};"
        : "+f"(c[0]), "+f"(c[1]), "+f"(c[2]), "+f"(c[3])
        : "r"(a[0]), "r"(a[1]), "r"(a[2]), "r"(a[3]), "r"(b[0]), "r"(b[1]));
}

// ---------------- K0: ragged bookkeeping ------------------------------------
__global__ void init_offsets_k(const void* __restrict__ counts) {
    if (threadIdx.x == 0 && blockIdx.x == 0) {
        const int* c32 = (const int*)counts;
        const long long* c64 = (const long long*)counts;
        long long s = 0;
        bool ok32 = true;
        for (int b = 0; b < NB; b++) {
            int v = c32[b];
            if (v < 0 || v > NMAX) ok32 = false;
            s += v;
        }
        if (s != TOT) ok32 = false;
        int acc = 0;
        for (int b = 0; b < NB; b++) {
            int c = ok32 ? c32[b] : (int)c64[b];
            if (c < 0) c = 0;
            if (c > NMAX) c = NMAX;
            g_off[b] = acc;
            g_cnt[b] = c;
            acc += c;
        }
    }
}

// ---------------- prep: split W_c into bf16 hi/lo, pad K --------------------
__global__ void __launch_bounds__(256) split_w_k(const float* __restrict__ Wc) {
    int id = blockIdx.x * 256 + threadIdx.x;
    if (id >= NGR * GF * CPAD) return;
    int cp = id % CPAD;
    int fg = id / CPAD;
    float v = (cp < DIN) ? Wc[(long long)fg * DIN + cp] : 0.f;
    __nv_bfloat16 h = __float2bfloat16(v);
    __nv_bfloat16 l = __float2bfloat16(v - __bfloat162float(h));
    g_w_hi[id] = h;
    g_w_lo[id] = l;
}

// ---------------- prep: transpose+split fm [b][c][s] -> [b][s][c] -----------
__global__ void __launch_bounds__(256) split_fm_k(const float* __restrict__ fm) {
    __shared__ float tile[32][33];
    int b = blockIdx.z;
    int s0 = blockIdx.x * 32, c0 = blockIdx.y * 32;
    int tx = threadIdx.x, ty = threadIdx.y;     // (32, 8)

#pragma unroll
    for (int i = 0; i < 4; i++) {
        int c = c0 + ty + i * 8;
        int s = s0 + tx;
        float v = 0.f;
        if (c < DIN && s < SS) v = fm[((long long)b * DIN + c) * SS + s];
        tile[ty + i * 8][tx] = v;
    }
    __syncthreads();
#pragma unroll
    for (int i = 0; i < 4; i++) {
        int s = s0 + ty + i * 8;
        int c = c0 + tx;
        float v = tile[tx][ty + i * 8];
        __nv_bfloat16 h = __float2bfloat16(v);
        __nv_bfloat16 l = __float2bfloat16(v - __bfloat162float(h));
        long long o = ((long long)b * SPAD + s) * CPAD + c;
        g_fmT_hi[o] = h;
        g_fmT_lo[o] = l;
    }
}

// ---------------- K2: ctx via mma.sync bf16 (3-term split) ------------------
// C[f][s] = sum_c W[g][f][c] * fmT[b][s][c]; M=f(128/CTA), N=s(128/CTA), K=c.
__global__ void __launch_bounds__(256, 1)
ctx_mma_k(const float* __restrict__ bc) {
    extern __shared__ __align__(16) char sm[];

    int tid = threadIdx.x;
    int lane = tid & 31, wid = tid >> 5;
    int bx = blockIdx.x;
    int stile = bx % STILES;
    int mtile = bx / STILES;
    int z = blockIdx.y;
    int b = z >> 2, g = z & 3;

    uint32_t sb = smem_u32(sm);

    const char* Ahc = (const char*)(g_w_hi + ((long long)g * GF + mtile * 128) * CPAD);
    const char* Alc = (const char*)(g_w_lo + ((long long)g * GF + mtile * 128) * CPAD);
    const char* Bhc = (const char*)(g_fmT_hi + ((long long)b * SPAD + stile * 128) * CPAD);
    const char* Blc = (const char*)(g_fmT_lo + ((long long)b * SPAD + stile * 128) * CPAD);

    // per-thread load slots: 2 rows of 16B per tile per stage
    int id0 = tid, id1 = tid + 256;
    int row0 = id0 >> 2, ci0 = id0 & 3;
    int row1 = id1 >> 2, ci1 = id1 & 3;
    uint32_t d0 = row0 * RS + ci0 * 16;
    uint32_t d1 = row1 * RS + ci1 * 16;
    long long so0 = (long long)row0 * (CPAD * 2) + ci0 * 16;
    long long so1 = (long long)row1 * (CPAD * 2) + ci1 * 16;

    // warp tile: warpM in 0..3 (32 f rows), warpN in 0..1 (64 s cols)
    int warpM = wid & 3, warpN = wid >> 2;
    int m0w = warpM * 32;
    int n0w = warpN * 64;

    // ldmatrix per-thread offsets (within a tile)
    uint32_t aOff[2], bOff[4];
#pragma unroll
    for (int i = 0; i < 2; i++)
        aOff[i] = (m0w + i * 16 + (lane & 15)) * RS + (lane >> 4) * 16;
#pragma unroll
    for (int jj = 0; jj < 4; jj++)
        bOff[jj] = (n0w + jj * 16 + (lane & 15)) * RS + (lane >> 4) * 16;

    float acc[2][8][4];
#pragma unroll
    for (int i = 0; i < 2; i++)
#pragma unroll
        for (int j = 0; j < 8; j++)
#pragma unroll
            for (int q = 0; q < 4; q++) acc[i][j][q] = 0.f;

    // ---- prologue: stage 0
    {
        long long cs = 0;
        uint32_t bo = 0;
        cp16(sb + bo + AH_OFF + d0, Ahc + so0 + cs);
        cp16(sb + bo + AH_OFF + d1, Ahc + so1 + cs);
        cp16(sb + bo + AL_OFF + d0, Alc + so0 + cs);
        cp16(sb + bo + AL_OFF + d1, Alc + so1 + cs);
        cp16(sb + bo + BH_OFF + d0, Bhc + so0 + cs);
        cp16(sb + bo + BH_OFF + d1, Bhc + so1 + cs);
        cp16(sb + bo + BL_OFF + d0, Blc + so0 + cs);
        cp16(sb + bo + BL_OFF + d1, Blc + so1 + cs);
        cp_commit();
    }

    for (int chunk = 0; chunk < KCHUNKS; chunk++) {
        uint32_t bo = (chunk & 1) ? STAGE_B : 0;
        // issue next stage
        if (chunk + 1 < KCHUNKS) {
            long long cs = (long long)(chunk + 1) * 64;
            uint32_t nbo = ((chunk + 1) & 1) ? STAGE_B : 0;
            cp16(sb + nbo + AH_OFF + d0, Ahc + so0 + cs);
            cp16(sb + nbo + AH_OFF + d1, Ahc + so1 + cs);
            cp16(sb + nbo + AL_OFF + d0, Alc + so0 + cs);
            cp16(sb + nbo + AL_OFF + d1, Alc + so1 + cs);
            cp16(sb + nbo + BH_OFF + d0, Bhc + so0 + cs);
            cp16(sb + nbo + BH_OFF + d1, Bhc + so1 + cs);
            cp16(sb + nbo + BL_OFF + d0, Blc + so0 + cs);
            cp16(sb + nbo + BL_OFF + d1, Blc + so1 + cs);
            cp_commit();
            cp_wait<1>();
        } else {
            cp_wait<0>();
        }
        __syncthreads();

#pragma unroll
        for (int ks = 0; ks < 2; ks++) {
            uint32_t kb = ks * 32;
            uint32_t ah[2][4], al[2][4];
#pragma unroll
            for (int i = 0; i < 2; i++) {
                ldsm4(ah[i][0], ah[i][1], ah[i][2], ah[i][3],
                      sb + bo + AH_OFF + aOff[i] + kb);
                ldsm4(al[i][0], al[i][1], al[i][2], al[i][3],
                      sb + bo + AL_OFF + aOff[i] + kb);
            }
            uint32_t bh[8][2], bl[8][2];
#pragma unroll
            for (int jj = 0; jj < 4; jj++) {
                uint32_t t0, t1, t2, t3;
                ldsm4(t0, t1, t2, t3, sb + bo + BH_OFF + bOff[jj] + kb);
                bh[2 * jj][0] = t0; bh[2 * jj][1] = t2;
                bh[2 * jj + 1][0] = t1; bh[2 * jj + 1][1] = t3;
                ldsm4(t0, t1, t2, t3, sb + bo + BL_OFF + bOff[jj] + kb);
                bl[2 * jj][0] = t0; bl[2 * jj][1] = t2;
                bl[2 * jj + 1][0] = t1; bl[2 * jj + 1][1] = t3;
            }
#pragma unroll
            for (int i = 0; i < 2; i++)
#pragma unroll
                for (int j = 0; j < 8; j++) {
                    mma_bf16(acc[i][j], ah[i], bh[j]);
                    mma_bf16(acc[i][j], ah[i], bl[j]);
                    mma_bf16(acc[i][j], al[i], bh[j]);
                }
        }
        __syncthreads();
    }

    // ---- epilogue: write C + bias, guard s < SS
    float* Cz = g_ctx + (long long)z * GF * SS;
#pragma unroll
    for (int i = 0; i < 2; i++) {
        int f0 = mtile * 128 + m0w + i * 16 + (lane >> 2);
        float bias0 = bc[g * GF + f0];
        float bias1 = bc[g * GF + f0 + 8];
#pragma unroll
        for (int j = 0; j < 8; j++) {
            int s0 = stile * 128 + n0w + j * 8 + 2 * (lane & 3);
            if (s0 < SS) {
                float2 v0 = make_float2(acc[i][j][0] + bias0, acc[i][j][1] + bias0);
                float2 v1 = make_float2(acc[i][j][2] + bias1, acc[i][j][3] + bias1);
                *(float2*)(Cz + (long long)f0 * SS + s0) = v0;
                *(float2*)(Cz + (long long)(f0 + 8) * SS + s0) = v1;
            }
        }
    }
}

// ---------------- generic GEMM: C[M][N] = A[M][K] * B[N][K]^T (+bias,+relu) -
__global__ void __launch_bounds__(256) gemm_nt_k(
    const float* __restrict__ A, int lda, long long aZ,
    const float* __restrict__ Bm, int ldb, long long bZ,
    const float* __restrict__ bias,
    float* __restrict__ C, int ldc, long long cZ,
    int K, int doRelu)
{
    int z = blockIdx.z;
    A  += (long long)z * aZ;
    Bm += (long long)z * bZ;
    C  += (long long)z * cZ;

    __shared__ __align__(16) float As[32][33];
    __shared__ __align__(16) float Bs[32][65];

    int tid = threadIdx.x;
    int m0 = blockIdx.x * 32;
    int n0 = blockIdx.y * 64;
    int tx = tid % 64;
    int ty = tid / 64;

    float acc[8];
#pragma unroll
    for (int i = 0; i < 8; i++) acc[i] = 0.f;

    for (int k0 = 0; k0 < K; k0 += 32) {
#pragma unroll
        for (int t = 0; t < 4; t++) {
            int lin = tid + 256 * t;
            int k = lin & 31, m = lin >> 5;
            As[k][m] = A[(m0 + m) * (long long)lda + k0 + k];
        }
#pragma unroll
        for (int t = 0; t < 8; t++) {
            int lin = tid + 256 * t;
            int k = lin & 31, n = lin >> 5;
            Bs[k][n] = Bm[(n0 + n) * (long long)ldb + k0 + k];
        }
        __syncthreads();
#pragma unroll
        for (int k = 0; k < 32; k++) {
            float bv = Bs[k][tx];
#pragma unroll
            for (int i = 0; i < 8; i++)
                acc[i] += As[k][ty + 4 * i] * bv;
        }
        __syncthreads();
    }

    float bb = bias ? bias[n0 + tx] : 0.f;
#pragma unroll
    for (int i = 0; i < 8; i++) {
        int m = m0 + ty + 4 * i;
        float v = acc[i] + bb;
        if (doRelu) v = fmaxf(v, 0.f);
        C[m * (long long)ldc + n0 + tx] = v;
    }
}

// ---------------- K3: adj logits ---------------------------------------------
__global__ void __launch_bounds__(256) adj_logits_k() {
    int g = blockIdx.y, b = blockIdx.z;
    __shared__ __align__(16) float a_s[GF * NMAX];
    int tid = threadIdx.x;
    int cnt = g_cnt[b], off = g_off[b];

    for (int idx = tid; idx < GF * NMAX; idx += 256) {
        int n = idx >> 8, f = idx & 255;
        float v = 0.f;
        if (n < cnt) v = g_emb[(off + n) * (NGR * GF) + g * GF + f];
        a_s[f * NMAX + n] = v;
    }
    __syncthreads();

    int s = blockIdx.x * 256 + tid;
    if (s >= SS) return;

    const float* ctxp = g_ctx + ((long long)(b * NGR + g)) * GF * SS + s;
    float acc[NMAX];
#pragma unroll
    for (int n = 0; n < NMAX; n++) acc[n] = 0.f;

    const float4* ap = (const float4*)a_s;
#pragma unroll 4
    for (int f = 0; f < GF; f++) {
        float v = ctxp[f * SS];
        float4 a0 = ap[f * 4 + 0];
        float4 a1 = ap[f * 4 + 1];
        float4 a2 = ap[f * 4 + 2];
        float4 a3 = ap[f * 4 + 3];
        acc[0]  += v * a0.x;  acc[1]  += v * a0.y;  acc[2]  += v * a0.z;  acc[3]  += v * a0.w;
        acc[4]  += v * a1.x;  acc[5]  += v * a1.y;  acc[6]  += v * a1.z;  acc[7]  += v * a1.w;
        acc[8]  += v * a2.x;  acc[9]  += v * a2.y;  acc[10] += v * a2.z;  acc[11] += v * a2.w;
        acc[12] += v * a3.x;  acc[13] += v * a3.y;  acc[14] += v * a3.z;  acc[15] += v * a3.w;
    }

    float* adjp = g_adj + ((long long)(b * NGR + g)) * NMAX * SS + s;
#pragma unroll
    for (int n = 0; n < NMAX; n++) adjp[n * SS] = acc[n];
}

// ---------------- K4: softmax -------------------------------------------------
__global__ void __launch_bounds__(256) softmax_k() {
    int n = blockIdx.x, g = blockIdx.y, b = blockIdx.z;
    if (n >= g_cnt[b]) return;
    float* row = g_adj + ((long long)((b * NGR + g) * NMAX + n)) * SS;
    int tid = threadIdx.x;
    __shared__ float red[8];

    float mx = -1e30f;
    for (int s = tid; s < SS; s += 256) mx = fmaxf(mx, row[s]);
#pragma unroll
    for (int o = 16; o > 0; o >>= 1) mx = fmaxf(mx, __shfl_xor_sync(0xffffffffu, mx, o));
    if ((tid & 31) == 0) red[tid >> 5] = mx;
    __syncthreads();
    if (tid < 32) {
        float v = (tid < 8) ? red[tid] : -1e30f;
#pragma unroll
        for (int o = 4; o > 0; o >>= 1) v = fmaxf(v, __shfl_xor_sync(0xffffffffu, v, o));
        if (tid == 0) red[0] = v;
    }
    __syncthreads();
    mx = red[0];
    __syncthreads();

    float sum = 0.f;
    for (int s = tid; s < SS; s += 256) {
        float e = __expf(row[s] - mx);
        row[s] = e;
        sum += e;
    }
#pragma unroll
    for (int o = 16; o > 0; o >>= 1) sum += __shfl_xor_sync(0xffffffffu, sum, o);
    if ((tid & 31) == 0) red[tid >> 5] = sum;
    __syncthreads();
    if (tid < 32) {
        float v = (tid < 8) ? red[tid] : 0.f;
#pragma unroll
        for (int o = 4; o > 0; o >>= 1) v += __shfl_xor_sync(0xffffffffu, v, o);
        if (tid == 0) red[0] = v;
    }
    __syncthreads();
    float inv = 1.f / red[0];
    for (int s = tid; s < SS; s += 256) row[s] *= inv;
}

// ---------------- K5: aggregate + residual -----------------------------------
__global__ void __launch_bounds__(256) aggregate_k() {
    int z = blockIdx.y;
    int b = z >> 2, g = z & 3;
    int f0 = blockIdx.x * 64;

    __shared__ __align__(16) float adjS[NMAX][33];
    __shared__ __align__(16) float ctxS[32][65];

    const float* adjp = g_adj + (long long)z * NMAX * SS;
    const float* ctxp = g_ctx + (long long)z * GF * SS;

    int tid = threadIdx.x;
    int fid = tid % 64, grp = tid / 64;
    float acc[4] = {0.f, 0.f, 0.f, 0.f};

    for (int s0 = 0; s0 < SS; s0 += 32) {
#pragma unroll
        for (int t = 0; t < 2; t++) {
            int lin = tid + 256 * t;
            int k = lin & 31, n = lin >> 5;
            adjS[n][k] = adjp[n * SS + s0 + k];
        }
#pragma unroll
        for (int t = 0; t < 8; t++) {
            int lin = tid + 256 * t;
            int k = lin & 31, i = lin >> 5;
            ctxS[k][i] = ctxp[(f0 + i) * SS + s0 + k];
        }
        __syncthreads();
#pragma unroll
        for (int k = 0; k < 32; k++) {
            float bv = ctxS[k][fid];
#pragma unroll
            for (int j = 0; j < 4; j++)
                acc[j] += adjS[grp * 4 + j][k] * bv;
        }
        __syncthreads();
    }

    int cnt = g_cnt[b], off = g_off[b];
#pragma unroll
    for (int j = 0; j < 4; j++) {
        int n = grp * 4 + j;
        if (n < cnt) {
            long long idx = (long long)(off + n) * (NGR * GF) + g * GF + f0 + fid;
            g_flat[idx] = acc[j] + g_emb[idx];
        }
    }
}

// ---------------- launch ----------------------------------------------------
extern "C" void kernel_launch(void* const* d_in, const int* in_sizes, int n_in,
                              void* d_out, int out_size) {
    const float* actor = (const float*)d_in[0];
    const float* fmap  = (const float*)d_in[1];
    const float* W_a   = (const float*)d_in[2];
    const float* b_a   = (const float*)d_in[3];
    const float* W_c   = (const float*)d_in[4];
    const float* b_c   = (const float*)d_in[5];
    const float* W_h   = (const float*)d_in[6];
    const void*  counts = d_in[7];
    int nbias = 0;
    for (int i = 0; i < n_in; i++) {
        switch (in_sizes[i]) {
            case TOT * IDIM:      actor = (const float*)d_in[i]; break;
            case NB * DIN * SS:   fmap  = (const float*)d_in[i]; break;
            case NGR * GF * IDIM: W_a   = (const float*)d_in[i]; break;
            case NGR * GF * DIN:  W_c   = (const float*)d_in[i]; break;
            case NGR * GF * GF:   W_h   = (const float*)d_in[i]; break;
            case NGR * GF:
                if (nbias++ == 0) b_a = (const float*)d_in[i];
                else              b_c = (const float*)d_in[i];
                break;
            case NB:              counts = d_in[i]; break;
            default: break;
        }
    }
    float* out = (float*)d_out;

    float *emb_p, *flat_p;
    cudaGetSymbolAddress((void**)&emb_p, g_emb);
    cudaGetSymbolAddress((void**)&flat_p, g_flat);

    cudaFuncSetAttribute(ctx_mma_k, cudaFuncAttributeMaxDynamicSharedMemorySize,
                         SMEM_DYN);

    init_offsets_k<<<1, 32>>>(counts);

    // prep: splits + transpose
    split_w_k<<<(NGR * GF * CPAD + 255) / 256, 256>>>(W_c);
    split_fm_k<<<dim3(SPAD / 32, CPAD / 32, NB), dim3(32, 8)>>>(fmap);

    // K1: emb (M=160, N=1024, K=1024)
    gemm_nt_k<<<dim3(5, 16, 1), 256>>>(actor, IDIM, 0,
                                       W_a, IDIM, 0,
                                       b_a,
                                       emb_p, NGR * GF, 0,
                                       IDIM, 0);

    // K2: ctx via mma.sync bf16 split
    ctx_mma_k<<<dim3(STILES * MTILES, NB * NGR), 256, SMEM_DYN>>>(b_c);

    // K3..K6 unchanged
    adj_logits_k<<<dim3(7, NGR, NB), 256>>>();
    softmax_k<<<dim3(NMAX, NGR, NB), 256>>>();
    aggregate_k<<<dim3(4, 64), 256>>>();
    gemm_nt_k<<<dim3(5, 4, 4), 256>>>(flat_p, NGR * GF, GF,
                                      W_h, GF, (long long)GF * GF,
                                      nullptr,
                                      out, NGR * GF, GF,
                                      GF, 1);
}

// round 6
// speedup vs baseline: 2.1105x; 1.0088x over previous
#include <cuda_runtime.h>
#include <cuda_bf16.h>
#include <cstdint>

// Problem constants
#define NGR 4
#define GF 256
#define DIN 834
#define SS 1568
#define NB 16
#define TOT 160
#define IDIM 1024
#define NMAX 16

// padded dims for MMA
#define CPAD 896            // K padded (28 chunks of 32)
#define SPAD 1664           // s padded (13 tiles of 128)
#define KCHUNKS 28
#define STILES 13
#define MTILES 2            // 256 f / 128

// smem layout for ctx_mma_k: 80B row stride, 128 rows per tile
#define RS 80
#define TILE_B (128 * RS)   // 10240
#define AH_OFF 0
#define AL_OFF (TILE_B)
#define BH_OFF (2 * TILE_B)
#define BL_OFF (3 * TILE_B)
#define STAGE_B (4 * TILE_B)        // 40960
#define SMEM_DYN (2 * STAGE_B)      // 81920

#define KSPLIT 4

// ---------------- scratch (static device globals) --------------------------
__device__ float g_emb[TOT * NGR * GF];
__device__ float g_embP[KSPLIT * TOT * NGR * GF];  // split-K partials
__device__ float g_ctx[NB * NGR * GF * SS];        // [z][f][s]
__device__ float g_adj[NB * NGR * NMAX * SS];
__device__ float g_flat[TOT * NGR * GF];
__device__ int   g_off[NB];
__device__ int   g_cnt[NB];
__device__ __nv_bfloat16 g_fmT_hi[(long long)NB * SPAD * CPAD];  // [b][s][c]
__device__ __nv_bfloat16 g_fmT_lo[(long long)NB * SPAD * CPAD];
__device__ __nv_bfloat16 g_w_hi[NGR * GF * CPAD];                // [g][f][c]
__device__ __nv_bfloat16 g_w_lo[NGR * GF * CPAD];

// ---------------- PTX helpers (baseline ISA only) ---------------------------
__device__ __forceinline__ uint32_t smem_u32(const void* p) {
    uint32_t a;
    asm("{ .reg .u64 t; cvta.to.shared.u64 t, %1; cvt.u32.u64 %0, t; }"
        : "=r"(a) : "l"(p));
    return a;
}
__device__ __forceinline__ void cp16(uint32_t dst, const void* src) {
    asm volatile("cp.async.cg.shared.global [%0], [%1], 16;"
                 :: "r"(dst), "l"(src) : "memory");
}
__device__ __forceinline__ void cp_commit() {
    asm volatile("cp.async.commit_group;" ::: "memory");
}
template <int N>
__device__ __forceinline__ void cp_wait() {
    asm volatile("cp.async.wait_group %0;" :: "n"(N) : "memory");
}
__device__ __forceinline__ void ldsm4(uint32_t& r0, uint32_t& r1, uint32_t& r2,
                                      uint32_t& r3, uint32_t a) {
    asm volatile("ldmatrix.sync.aligned.m8n8.x4.shared.b16 {%0,%1,%2,%3}, [%4];"
                 : "=r"(r0), "=r"(r1), "=r"(r2), "=r"(r3) : "r"(a));
}
__device__ __forceinline__ void mma_bf16(float* c, const uint32_t* a,
                                         const uint32_t* b) {
    asm volatile(
        "mma.sync.aligned.m16n8k16.row.col.f32.bf16.bf16.f32 "
        "{%0,%1,%2,%3}, {%4,%5,%6,%7}, {%8,%9}, {%0,%1,%2,%3};"
        : "+f"(c[0]), "+f"(c[1]), "+f"(c[2]), "+f"(c[3])
        : "r"(a[0]), "r"(a[1]), "r"(a[2]), "r"(a[3]), "r"(b[0]), "r"(b[1]));
}

// ---------------- K0: ragged bookkeeping ------------------------------------
__global__ void init_offsets_k(const void* __restrict__ counts) {
    if (threadIdx.x == 0 && blockIdx.x == 0) {
        const int* c32 = (const int*)counts;
        const long long* c64 = (const long long*)counts;
        long long s = 0;
        bool ok32 = true;
        for (int b = 0; b < NB; b++) {
            int v = c32[b];
            if (v < 0 || v > NMAX) ok32 = false;
            s += v;
        }
        if (s != TOT) ok32 = false;
        int acc = 0;
        for (int b = 0; b < NB; b++) {
            int c = ok32 ? c32[b] : (int)c64[b];
            if (c < 0) c = 0;
            if (c > NMAX) c = NMAX;
            g_off[b] = acc;
            g_cnt[b] = c;
            acc += c;
        }
    }
}

// ---------------- prep: split W_c into bf16 hi/lo, pad K --------------------
__global__ void __launch_bounds__(256) split_w_k(const float* __restrict__ Wc) {
    int id = blockIdx.x * 256 + threadIdx.x;
    if (id >= NGR * GF * CPAD) return;
    int cp = id % CPAD;
    int fg = id / CPAD;
    float v = (cp < DIN) ? Wc[(long long)fg * DIN + cp] : 0.f;
    __nv_bfloat16 h = __float2bfloat16(v);
    __nv_bfloat16 l = __float2bfloat16(v - __bfloat162float(h));
    g_w_hi[id] = h;
    g_w_lo[id] = l;
}

// ---------------- prep: transpose+split fm [b][c][s] -> [b][s][c] -----------
__global__ void __launch_bounds__(256) split_fm_k(const float* __restrict__ fm) {
    __shared__ float tile[32][33];
    int b = blockIdx.z;
    int s0 = blockIdx.x * 32, c0 = blockIdx.y * 32;
    int tx = threadIdx.x, ty = threadIdx.y;     // (32, 8)

#pragma unroll
    for (int i = 0; i < 4; i++) {
        int c = c0 + ty + i * 8;
        int s = s0 + tx;
        float v = 0.f;
        if (c < DIN && s < SS) v = fm[((long long)b * DIN + c) * SS + s];
        tile[ty + i * 8][tx] = v;
    }
    __syncthreads();
#pragma unroll
    for (int i = 0; i < 4; i++) {
        int s = s0 + ty + i * 8;
        int c = c0 + tx;
        float v = tile[tx][ty + i * 8];
        __nv_bfloat16 h = __float2bfloat16(v);
        __nv_bfloat16 l = __float2bfloat16(v - __bfloat162float(h));
        long long o = ((long long)b * SPAD + s) * CPAD + c;
        g_fmT_hi[o] = h;
        g_fmT_lo[o] = l;
    }
}

// ---------------- emb split-K partial GEMM ----------------------------------
// part[z][m][n] = sum_{k in z-chunk} actor[m][k] * W_a[n][k]
__global__ void __launch_bounds__(256) emb_part_k(
    const float* __restrict__ A, const float* __restrict__ Bm)
{
    int z = blockIdx.z;                 // k-split
    int kbase = z * (IDIM / KSPLIT);

    __shared__ __align__(16) float As[32][33];
    __shared__ __align__(16) float Bs[32][65];

    int tid = threadIdx.x;
    int m0 = blockIdx.x * 32;
    int n0 = blockIdx.y * 64;
    int tx = tid % 64;
    int ty = tid / 64;

    float acc[8];
#pragma unroll
    for (int i = 0; i < 8; i++) acc[i] = 0.f;

    for (int k0 = kbase; k0 < kbase + IDIM / KSPLIT; k0 += 32) {
#pragma unroll
        for (int t = 0; t < 4; t++) {
            int lin = tid + 256 * t;
            int k = lin & 31, m = lin >> 5;
            As[k][m] = A[(m0 + m) * IDIM + k0 + k];
        }
#pragma unroll
        for (int t = 0; t < 8; t++) {
            int lin = tid + 256 * t;
            int k = lin & 31, n = lin >> 5;
            Bs[k][n] = Bm[(n0 + n) * IDIM + k0 + k];
        }
        __syncthreads();
#pragma unroll
        for (int k = 0; k < 32; k++) {
            float bv = Bs[k][tx];
#pragma unroll
            for (int i = 0; i < 8; i++)
                acc[i] += As[k][ty + 4 * i] * bv;
        }
        __syncthreads();
    }

    float* P = g_embP + (long long)z * TOT * NGR * GF;
#pragma unroll
    for (int i = 0; i < 8; i++) {
        int m = m0 + ty + 4 * i;
        P[m * (NGR * GF) + n0 + tx] = acc[i];
    }
}

// reduce partials + bias
__global__ void __launch_bounds__(256) emb_reduce_k(const float* __restrict__ ba) {
    int id = blockIdx.x * 256 + threadIdx.x;
    if (id >= TOT * NGR * GF) return;
    float v = ba[id & (NGR * GF - 1)];
#pragma unroll
    for (int z = 0; z < KSPLIT; z++)
        v += g_embP[z * (TOT * NGR * GF) + id];
    g_emb[id] = v;
}

// ---------------- K2: ctx via mma.sync bf16 (3-term split) ------------------
__global__ void __launch_bounds__(256, 1)
ctx_mma_k(const float* __restrict__ bc) {
    extern __shared__ __align__(16) char sm[];

    int tid = threadIdx.x;
    int lane = tid & 31, wid = tid >> 5;
    int bx = blockIdx.x;
    int stile = bx % STILES;
    int mtile = bx / STILES;
    int z = blockIdx.y;
    int b = z >> 2, g = z & 3;

    uint32_t sb = smem_u32(sm);

    const char* Ahc = (const char*)(g_w_hi + ((long long)g * GF + mtile * 128) * CPAD);
    const char* Alc = (const char*)(g_w_lo + ((long long)g * GF + mtile * 128) * CPAD);
    const char* Bhc = (const char*)(g_fmT_hi + ((long long)b * SPAD + stile * 128) * CPAD);
    const char* Blc = (const char*)(g_fmT_lo + ((long long)b * SPAD + stile * 128) * CPAD);

    int id0 = tid, id1 = tid + 256;
    int row0 = id0 >> 2, ci0 = id0 & 3;
    int row1 = id1 >> 2, ci1 = id1 & 3;
    uint32_t d0 = row0 * RS + ci0 * 16;
    uint32_t d1 = row1 * RS + ci1 * 16;
    long long so0 = (long long)row0 * (CPAD * 2) + ci0 * 16;
    long long so1 = (long long)row1 * (CPAD * 2) + ci1 * 16;

    int warpM = wid & 3, warpN = wid >> 2;
    int m0w = warpM * 32;
    int n0w = warpN * 64;

    uint32_t aOff[2], bOff[4];
#pragma unroll
    for (int i = 0; i < 2; i++)
        aOff[i] = (m0w + i * 16 + (lane & 15)) * RS + (lane >> 4) * 16;
#pragma unroll
    for (int jj = 0; jj < 4; jj++)
        bOff[jj] = (n0w + jj * 16 + (lane & 15)) * RS + (lane >> 4) * 16;

    float acc[2][8][4];
#pragma unroll
    for (int i = 0; i < 2; i++)
#pragma unroll
        for (int j = 0; j < 8; j++)
#pragma unroll
            for (int q = 0; q < 4; q++) acc[i][j][q] = 0.f;

    {
        long long cs = 0;
        uint32_t bo = 0;
        cp16(sb + bo + AH_OFF + d0, Ahc + so0 + cs);
        cp16(sb + bo + AH_OFF + d1, Ahc + so1 + cs);
        cp16(sb + bo + AL_OFF + d0, Alc + so0 + cs);
        cp16(sb + bo + AL_OFF + d1, Alc + so1 + cs);
        cp16(sb + bo + BH_OFF + d0, Bhc + so0 + cs);
        cp16(sb + bo + BH_OFF + d1, Bhc + so1 + cs);
        cp16(sb + bo + BL_OFF + d0, Blc + so0 + cs);
        cp16(sb + bo + BL_OFF + d1, Blc + so1 + cs);
        cp_commit();
    }

    for (int chunk = 0; chunk < KCHUNKS; chunk++) {
        uint32_t bo = (chunk & 1) ? STAGE_B : 0;
        if (chunk + 1 < KCHUNKS) {
            long long cs = (long long)(chunk + 1) * 64;
            uint32_t nbo = ((chunk + 1) & 1) ? STAGE_B : 0;
            cp16(sb + nbo + AH_OFF + d0, Ahc + so0 + cs);
            cp16(sb + nbo + AH_OFF + d1, Ahc + so1 + cs);
            cp16(sb + nbo + AL_OFF + d0, Alc + so0 + cs);
            cp16(sb + nbo + AL_OFF + d1, Alc + so1 + cs);
            cp16(sb + nbo + BH_OFF + d0, Bhc + so0 + cs);
            cp16(sb + nbo + BH_OFF + d1, Bhc + so1 + cs);
            cp16(sb + nbo + BL_OFF + d0, Blc + so0 + cs);
            cp16(sb + nbo + BL_OFF + d1, Blc + so1 + cs);
            cp_commit();
            cp_wait<1>();
        } else {
            cp_wait<0>();
        }
        __syncthreads();

#pragma unroll
        for (int ks = 0; ks < 2; ks++) {
            uint32_t kb = ks * 32;
            uint32_t ah[2][4], al[2][4];
#pragma unroll
            for (int i = 0; i < 2; i++) {
                ldsm4(ah[i][0], ah[i][1], ah[i][2], ah[i][3],
                      sb + bo + AH_OFF + aOff[i] + kb);
                ldsm4(al[i][0], al[i][1], al[i][2], al[i][3],
                      sb + bo + AL_OFF + aOff[i] + kb);
            }
            uint32_t bh[8][2], bl[8][2];
#pragma unroll
            for (int jj = 0; jj < 4; jj++) {
                uint32_t t0, t1, t2, t3;
                ldsm4(t0, t1, t2, t3, sb + bo + BH_OFF + bOff[jj] + kb);
                bh[2 * jj][0] = t0; bh[2 * jj][1] = t2;
                bh[2 * jj + 1][0] = t1; bh[2 * jj + 1][1] = t3;
                ldsm4(t0, t1, t2, t3, sb + bo + BL_OFF + bOff[jj] + kb);
                bl[2 * jj][0] = t0; bl[2 * jj][1] = t2;
                bl[2 * jj + 1][0] = t1; bl[2 * jj + 1][1] = t3;
            }
#pragma unroll
            for (int i = 0; i < 2; i++)
#pragma unroll
                for (int j = 0; j < 8; j++) {
                    mma_bf16(acc[i][j], ah[i], bh[j]);
                    mma_bf16(acc[i][j], ah[i], bl[j]);
                    mma_bf16(acc[i][j], al[i], bh[j]);
                }
        }
        __syncthreads();
    }

    float* Cz = g_ctx + (long long)z * GF * SS;
#pragma unroll
    for (int i = 0; i < 2; i++) {
        int f0 = mtile * 128 + m0w + i * 16 + (lane >> 2);
        float bias0 = bc[g * GF + f0];
        float bias1 = bc[g * GF + f0 + 8];
#pragma unroll
        for (int j = 0; j < 8; j++) {
            int s0 = stile * 128 + n0w + j * 8 + 2 * (lane & 3);
            if (s0 < SS) {
                float2 v0 = make_float2(acc[i][j][0] + bias0, acc[i][j][1] + bias0);
                float2 v1 = make_float2(acc[i][j][2] + bias1, acc[i][j][3] + bias1);
                *(float2*)(Cz + (long long)f0 * SS + s0) = v0;
                *(float2*)(Cz + (long long)(f0 + 8) * SS + s0) = v1;
            }
        }
    }
}

// ---------------- generic GEMM (head): C = A * B^T, relu --------------------
__global__ void __launch_bounds__(256) gemm_nt_k(
    const float* __restrict__ A, int lda, long long aZ,
    const float* __restrict__ Bm, int ldb, long long bZ,
    const float* __restrict__ bias,
    float* __restrict__ C, int ldc, long long cZ,
    int K, int doRelu)
{
    int z = blockIdx.z;
    A  += (long long)z * aZ;
    Bm += (long long)z * bZ;
    C  += (long long)z * cZ;

    __shared__ __align__(16) float As[32][33];
    __shared__ __align__(16) float Bs[32][65];

    int tid = threadIdx.x;
    int m0 = blockIdx.x * 32;
    int n0 = blockIdx.y * 64;
    int tx = tid % 64;
    int ty = tid / 64;

    float acc[8];
#pragma unroll
    for (int i = 0; i < 8; i++) acc[i] = 0.f;

    for (int k0 = 0; k0 < K; k0 += 32) {
#pragma unroll
        for (int t = 0; t < 4; t++) {
            int lin = tid + 256 * t;
            int k = lin & 31, m = lin >> 5;
            As[k][m] = A[(m0 + m) * (long long)lda + k0 + k];
        }
#pragma unroll
        for (int t = 0; t < 8; t++) {
            int lin = tid + 256 * t;
            int k = lin & 31, n = lin >> 5;
            Bs[k][n] = Bm[(n0 + n) * (long long)ldb + k0 + k];
        }
        __syncthreads();
#pragma unroll
        for (int k = 0; k < 32; k++) {
            float bv = Bs[k][tx];
#pragma unroll
            for (int i = 0; i < 8; i++)
                acc[i] += As[k][ty + 4 * i] * bv;
        }
        __syncthreads();
    }

    float bb = bias ? bias[n0 + tx] : 0.f;
#pragma unroll
    for (int i = 0; i < 8; i++) {
        int m = m0 + ty + 4 * i;
        float v = acc[i] + bb;
        if (doRelu) v = fmaxf(v, 0.f);
        C[m * (long long)ldc + n0 + tx] = v;
    }
}

// ---------------- K3: adj logits (2 s-columns per thread) -------------------
__global__ void __launch_bounds__(256) adj_logits_k() {
    int g = blockIdx.y, b = blockIdx.z;
    __shared__ __align__(16) float a_s[GF * NMAX];   // [f][n]
    int tid = threadIdx.x;
    int cnt = g_cnt[b], off = g_off[b];

    for (int idx = tid; idx < GF * NMAX; idx += 256) {
        int n = idx >> 8, f = idx & 255;
        float v = 0.f;
        if (n < cnt) v = g_emb[(off + n) * (NGR * GF) + g * GF + f];
        a_s[f * NMAX + n] = v;
    }
    __syncthreads();

    int s0 = blockIdx.x * 512 + tid;
    int s1 = s0 + 256;
    if (s0 >= SS) return;
    bool ok1 = (s1 < SS);
    int s1c = ok1 ? s1 : s0;   // safe load address

    const float* ctxp = g_ctx + ((long long)(b * NGR + g)) * GF * SS;
    float acc0[NMAX], acc1[NMAX];
#pragma unroll
    for (int n = 0; n < NMAX; n++) { acc0[n] = 0.f; acc1[n] = 0.f; }

    const float4* ap = (const float4*)a_s;
#pragma unroll 2
    for (int f = 0; f < GF; f++) {
        float x0 = ctxp[(long long)f * SS + s0];
        float x1 = ctxp[(long long)f * SS + s1c];
        float4 a0 = ap[f * 4 + 0];
        float4 a1 = ap[f * 4 + 1];
        float4 a2 = ap[f * 4 + 2];
        float4 a3 = ap[f * 4 + 3];
        acc0[0]  += x0 * a0.x;  acc0[1]  += x0 * a0.y;  acc0[2]  += x0 * a0.z;  acc0[3]  += x0 * a0.w;
        acc0[4]  += x0 * a1.x;  acc0[5]  += x0 * a1.y;  acc0[6]  += x0 * a1.z;  acc0[7]  += x0 * a1.w;
        acc0[8]  += x0 * a2.x;  acc0[9]  += x0 * a2.y;  acc0[10] += x0 * a2.z;  acc0[11] += x0 * a2.w;
        acc0[12] += x0 * a3.x;  acc0[13] += x0 * a3.y;  acc0[14] += x0 * a3.z;  acc0[15] += x0 * a3.w;
        acc1[0]  += x1 * a0.x;  acc1[1]  += x1 * a0.y;  acc1[2]  += x1 * a0.z;  acc1[3]  += x1 * a0.w;
        acc1[4]  += x1 * a1.x;  acc1[5]  += x1 * a1.y;  acc1[6]  += x1 * a1.z;  acc1[7]  += x1 * a1.w;
        acc1[8]  += x1 * a2.x;  acc1[9]  += x1 * a2.y;  acc1[10] += x1 * a2.z;  acc1[11] += x1 * a2.w;
        acc1[12] += x1 * a3.x;  acc1[13] += x1 * a3.y;  acc1[14] += x1 * a3.z;  acc1[15] += x1 * a3.w;
    }

    float* adjp = g_adj + ((long long)(b * NGR + g)) * NMAX * SS;
#pragma unroll
    for (int n = 0; n < NMAX; n++) {
        adjp[(long long)n * SS + s0] = acc0[n];
        if (ok1) adjp[(long long)n * SS + s1] = acc1[n];
    }
}

// ---------------- K4: softmax -------------------------------------------------
__global__ void __launch_bounds__(256) softmax_k() {
    int n = blockIdx.x, g = blockIdx.y, b = blockIdx.z;
    if (n >= g_cnt[b]) return;
    float* row = g_adj + ((long long)((b * NGR + g) * NMAX + n)) * SS;
    int tid = threadIdx.x;
    __shared__ float red[8];

    float mx = -1e30f;
    for (int s = tid; s < SS; s += 256) mx = fmaxf(mx, row[s]);
#pragma unroll
    for (int o = 16; o > 0; o >>= 1) mx = fmaxf(mx, __shfl_xor_sync(0xffffffffu, mx, o));
    if ((tid & 31) == 0) red[tid >> 5] = mx;
    __syncthreads();
    if (tid < 32) {
        float v = (tid < 8) ? red[tid] : -1e30f;
#pragma unroll
        for (int o = 4; o > 0; o >>= 1) v = fmaxf(v, __shfl_xor_sync(0xffffffffu, v, o));
        if (tid == 0) red[0] = v;
    }
    __syncthreads();
    mx = red[0];
    __syncthreads();

    float sum = 0.f;
    for (int s = tid; s < SS; s += 256) {
        float e = __expf(row[s] - mx);
        row[s] = e;
        sum += e;
    }
#pragma unroll
    for (int o = 16; o > 0; o >>= 1) sum += __shfl_xor_sync(0xffffffffu, sum, o);
    if ((tid & 31) == 0) red[tid >> 5] = sum;
    __syncthreads();
    if (tid < 32) {
        float v = (tid < 8) ? red[tid] : 0.f;
#pragma unroll
        for (int o = 4; o > 0; o >>= 1) v += __shfl_xor_sync(0xffffffffu, v, o);
        if (tid == 0) red[0] = v;
    }
    __syncthreads();
    float inv = 1.f / red[0];
    for (int s = tid; s < SS; s += 256) row[s] *= inv;
}

// ---------------- K5: aggregate + residual -----------------------------------
__global__ void __launch_bounds__(256) aggregate_k() {
    int z = blockIdx.y;
    int b = z >> 2, g = z & 3;
    int f0 = blockIdx.x * 64;

    __shared__ __align__(16) float adjS[NMAX][33];
    __shared__ __align__(16) float ctxS[32][65];

    const float* adjp = g_adj + (long long)z * NMAX * SS;
    const float* ctxp = g_ctx + (long long)z * GF * SS;

    int tid = threadIdx.x;
    int fid = tid % 64, grp = tid / 64;
    float acc[4] = {0.f, 0.f, 0.f, 0.f};

    for (int s0 = 0; s0 < SS; s0 += 32) {
#pragma unroll
        for (int t = 0; t < 2; t++) {
            int lin = tid + 256 * t;
            int k = lin & 31, n = lin >> 5;
            adjS[n][k] = adjp[n * SS + s0 + k];
        }
#pragma unroll
        for (int t = 0; t < 8; t++) {
            int lin = tid + 256 * t;
            int k = lin & 31, i = lin >> 5;
            ctxS[k][i] = ctxp[(f0 + i) * SS + s0 + k];
        }
        __syncthreads();
#pragma unroll
        for (int k = 0; k < 32; k++) {
            float bv = ctxS[k][fid];
#pragma unroll
            for (int j = 0; j < 4; j++)
                acc[j] += adjS[grp * 4 + j][k] * bv;
        }
        __syncthreads();
    }

    int cnt = g_cnt[b], off = g_off[b];
#pragma unroll
    for (int j = 0; j < 4; j++) {
        int n = grp * 4 + j;
        if (n < cnt) {
            long long idx = (long long)(off + n) * (NGR * GF) + g * GF + f0 + fid;
            g_flat[idx] = acc[j] + g_emb[idx];
        }
    }
}

// ---------------- launch ----------------------------------------------------
extern "C" void kernel_launch(void* const* d_in, const int* in_sizes, int n_in,
                              void* d_out, int out_size) {
    const float* actor = (const float*)d_in[0];
    const float* fmap  = (const float*)d_in[1];
    const float* W_a   = (const float*)d_in[2];
    const float* b_a   = (const float*)d_in[3];
    const float* W_c   = (const float*)d_in[4];
    const float* b_c   = (const float*)d_in[5];
    const float* W_h   = (const float*)d_in[6];
    const void*  counts = d_in[7];
    int nbias = 0;
    for (int i = 0; i < n_in; i++) {
        switch (in_sizes[i]) {
            case TOT * IDIM:      actor = (const float*)d_in[i]; break;
            case NB * DIN * SS:   fmap  = (const float*)d_in[i]; break;
            case NGR * GF * IDIM: W_a   = (const float*)d_in[i]; break;
            case NGR * GF * DIN:  W_c   = (const float*)d_in[i]; break;
            case NGR * GF * GF:   W_h   = (const float*)d_in[i]; break;
            case NGR * GF:
                if (nbias++ == 0) b_a = (const float*)d_in[i];
                else              b_c = (const float*)d_in[i];
                break;
            case NB:              counts = d_in[i]; break;
            default: break;
        }
    }
    float* out = (float*)d_out;

    float* flat_p;
    cudaGetSymbolAddress((void**)&flat_p, g_flat);

    cudaFuncSetAttribute(ctx_mma_k, cudaFuncAttributeMaxDynamicSharedMemorySize,
                         SMEM_DYN);

    // launch order chosen so ctx_mma_k is launch index 5 (ncu -s 5 -c 1)
    init_offsets_k<<<1, 32>>>(counts);                                    // 0
    split_w_k<<<(NGR * GF * CPAD + 255) / 256, 256>>>(W_c);               // 1
    split_fm_k<<<dim3(SPAD / 32, CPAD / 32, NB), dim3(32, 8)>>>(fmap);    // 2
    emb_part_k<<<dim3(5, 16, KSPLIT), 256>>>(actor, W_a);                 // 3
    emb_reduce_k<<<(TOT * NGR * GF + 255) / 256, 256>>>(b_a);             // 4
    ctx_mma_k<<<dim3(STILES * MTILES, NB * NGR), 256, SMEM_DYN>>>(b_c);   // 5
    adj_logits_k<<<dim3(4, NGR, NB), 256>>>();                            // 6
    softmax_k<<<dim3(NMAX, NGR, NB), 256>>>();                            // 7
    aggregate_k<<<dim3(4, 64), 256>>>();                                  // 8
    gemm_nt_k<<<dim3(5, 4, 4), 256>>>(flat_p, NGR * GF, GF,               // 9
                                      W_h, GF, (long long)GF * GF,
                                      nullptr,
                                      out, NGR * GF, GF,
                                      GF, 1);
}

// round 7
// speedup vs baseline: 2.2668x; 1.0741x over previous
#include <cuda_runtime.h>
#include <cuda_bf16.h>
#include <cstdint>

// Problem constants
#define NGR 4
#define GF 256
#define DIN 834
#define SS 1568
#define NB 16
#define TOT 160
#define IDIM 1024
#define NMAX 16

// padded dims for MMA
#define CPAD 896            // K padded (28 chunks of 32)
#define SPAD 1664           // s padded (13 tiles of 128)
#define KCHUNKS 28
#define STILES 13
#define MTILES 2            // 256 f / 128

// smem layout for ctx_mma_k: 80B row stride, 128 rows per tile
#define RS 80
#define TILE_B (128 * RS)   // 10240
#define AH_OFF 0
#define AL_OFF (TILE_B)
#define BH_OFF (2 * TILE_B)
#define BL_OFF (3 * TILE_B)
#define STAGE_B (4 * TILE_B)        // 40960
#define SMEM_DYN (2 * STAGE_B)      // 81920

#define KSPLIT 4

// ---------------- scratch (static device globals) --------------------------
__device__ float g_emb[TOT * NGR * GF];
__device__ float g_embP[KSPLIT * TOT * NGR * GF];  // split-K partials
__device__ float g_ctx[NB * NGR * GF * SS];        // [z][f][s]
__device__ float g_adj[NB * NGR * NMAX * SS];
__device__ float g_flat[TOT * NGR * GF];
__device__ int   g_off[NB];
__device__ int   g_cnt[NB];
__device__ __nv_bfloat16 g_fmT_hi[(long long)NB * SPAD * CPAD];  // [b][s][c]
__device__ __nv_bfloat16 g_fmT_lo[(long long)NB * SPAD * CPAD];
__device__ __nv_bfloat16 g_w_hi[NGR * GF * CPAD];                // [g][f][c]
__device__ __nv_bfloat16 g_w_lo[NGR * GF * CPAD];

// ---------------- PTX helpers (baseline ISA only) ---------------------------
__device__ __forceinline__ uint32_t smem_u32(const void* p) {
    uint32_t a;
    asm("{ .reg .u64 t; cvta.to.shared.u64 t, %1; cvt.u32.u64 %0, t; }"
        : "=r"(a) : "l"(p));
    return a;
}
__device__ __forceinline__ void cp16(uint32_t dst, const void* src) {
    asm volatile("cp.async.cg.shared.global [%0], [%1], 16;"
                 :: "r"(dst), "l"(src) : "memory");
}
__device__ __forceinline__ void cp_commit() {
    asm volatile("cp.async.commit_group;" ::: "memory");
}
template <int N>
__device__ __forceinline__ void cp_wait() {
    asm volatile("cp.async.wait_group %0;" :: "n"(N) : "memory");
}
__device__ __forceinline__ void ldsm4(uint32_t& r0, uint32_t& r1, uint32_t& r2,
                                      uint32_t& r3, uint32_t a) {
    asm volatile("ldmatrix.sync.aligned.m8n8.x4.shared.b16 {%0,%1,%2,%3}, [%4];"
                 : "=r"(r0), "=r"(r1), "=r"(r2), "=r"(r3) : "r"(a));
}
__device__ __forceinline__ void mma_bf16(float* c, const uint32_t* a,
                                         uint32_t b0, uint32_t b1) {
    asm volatile(
        "mma.sync.aligned.m16n8k16.row.col.f32.bf16.bf16.f32 "
        "{%0,%1,%2,%3}, {%4,%5,%6,%7}, {%8,%9}, {%0,%1,%2,%3};"
        : "+f"(c[0]), "+f"(c[1]), "+f"(c[2]), "+f"(c[3])
        : "r"(a[0]), "r"(a[1]), "r"(a[2]), "r"(a[3]), "r"(b0), "r"(b1));
}

// ---------------- K0: ragged bookkeeping ------------------------------------
__global__ void init_offsets_k(const void* __restrict__ counts) {
    if (threadIdx.x == 0 && blockIdx.x == 0) {
        const int* c32 = (const int*)counts;
        const long long* c64 = (const long long*)counts;
        long long s = 0;
        bool ok32 = true;
        for (int b = 0; b < NB; b++) {
            int v = c32[b];
            if (v < 0 || v > NMAX) ok32 = false;
            s += v;
        }
        if (s != TOT) ok32 = false;
        int acc = 0;
        for (int b = 0; b < NB; b++) {
            int c = ok32 ? c32[b] : (int)c64[b];
            if (c < 0) c = 0;
            if (c > NMAX) c = NMAX;
            g_off[b] = acc;
            g_cnt[b] = c;
            acc += c;
        }
    }
}

// ---------------- prep: split W_c into bf16 hi/lo, pad K --------------------
__global__ void __launch_bounds__(256) split_w_k(const float* __restrict__ Wc) {
    int id = blockIdx.x * 256 + threadIdx.x;
    if (id >= NGR * GF * CPAD) return;
    int cp = id % CPAD;
    int fg = id / CPAD;
    float v = (cp < DIN) ? Wc[(long long)fg * DIN + cp] : 0.f;
    __nv_bfloat16 h = __float2bfloat16(v);
    __nv_bfloat16 l = __float2bfloat16(v - __bfloat162float(h));
    g_w_hi[id] = h;
    g_w_lo[id] = l;
}

// ---------------- prep: transpose+split fm [b][c][s] -> [b][s][c] -----------
__global__ void __launch_bounds__(256) split_fm_k(const float* __restrict__ fm) {
    __shared__ float tile[32][33];
    int b = blockIdx.z;
    int s0 = blockIdx.x * 32, c0 = blockIdx.y * 32;
    int tx = threadIdx.x, ty = threadIdx.y;     // (32, 8)

#pragma unroll
    for (int i = 0; i < 4; i++) {
        int c = c0 + ty + i * 8;
        int s = s0 + tx;
        float v = 0.f;
        if (c < DIN && s < SS) v = fm[((long long)b * DIN + c) * SS + s];
        tile[ty + i * 8][tx] = v;
    }
    __syncthreads();
#pragma unroll
    for (int i = 0; i < 4; i++) {
        int s = s0 + ty + i * 8;
        int c = c0 + tx;
        float v = tile[tx][ty + i * 8];
        __nv_bfloat16 h = __float2bfloat16(v);
        __nv_bfloat16 l = __float2bfloat16(v - __bfloat162float(h));
        long long o = ((long long)b * SPAD + s) * CPAD + c;
        g_fmT_hi[o] = h;
        g_fmT_lo[o] = l;
    }
}

// ---------------- K2: ctx via mma.sync bf16 (3-term split), 2 CTA/SM --------
__global__ void __launch_bounds__(256, 2)
ctx_mma_k(const float* __restrict__ bc) {
    extern __shared__ __align__(16) char sm[];

    int tid = threadIdx.x;
    int lane = tid & 31, wid = tid >> 5;
    int bx = blockIdx.x;
    int stile = bx % STILES;
    int mtile = bx / STILES;
    int z = blockIdx.y;
    int b = z >> 2, g = z & 3;

    uint32_t sb = smem_u32(sm);

    const char* Ahc = (const char*)(g_w_hi + ((long long)g * GF + mtile * 128) * CPAD);
    const char* Alc = (const char*)(g_w_lo + ((long long)g * GF + mtile * 128) * CPAD);
    const char* Bhc = (const char*)(g_fmT_hi + ((long long)b * SPAD + stile * 128) * CPAD);
    const char* Blc = (const char*)(g_fmT_lo + ((long long)b * SPAD + stile * 128) * CPAD);

    int id0 = tid, id1 = tid + 256;
    int row0 = id0 >> 2, ci0 = id0 & 3;
    int row1 = id1 >> 2, ci1 = id1 & 3;
    uint32_t d0 = row0 * RS + ci0 * 16;
    uint32_t d1 = row1 * RS + ci1 * 16;
    long long so0 = (long long)row0 * (CPAD * 2) + ci0 * 16;
    long long so1 = (long long)row1 * (CPAD * 2) + ci1 * 16;

    int warpM = wid & 3, warpN = wid >> 2;
    int m0w = warpM * 32;
    int n0w = warpN * 64;

    uint32_t aOff[2], bOff[4];
#pragma unroll
    for (int i = 0; i < 2; i++)
        aOff[i] = (m0w + i * 16 + (lane & 15)) * RS + (lane >> 4) * 16;
#pragma unroll
    for (int jj = 0; jj < 4; jj++)
        bOff[jj] = (n0w + jj * 16 + (lane & 15)) * RS + (lane >> 4) * 16;

    float acc[2][8][4];
#pragma unroll
    for (int i = 0; i < 2; i++)
#pragma unroll
        for (int j = 0; j < 8; j++)
#pragma unroll
            for (int q = 0; q < 4; q++) acc[i][j][q] = 0.f;

    {
        uint32_t bo = 0;
        cp16(sb + bo + AH_OFF + d0, Ahc + so0);
        cp16(sb + bo + AH_OFF + d1, Ahc + so1);
        cp16(sb + bo + AL_OFF + d0, Alc + so0);
        cp16(sb + bo + AL_OFF + d1, Alc + so1);
        cp16(sb + bo + BH_OFF + d0, Bhc + so0);
        cp16(sb + bo + BH_OFF + d1, Bhc + so1);
        cp16(sb + bo + BL_OFF + d0, Blc + so0);
        cp16(sb + bo + BL_OFF + d1, Blc + so1);
        cp_commit();
    }

    for (int chunk = 0; chunk < KCHUNKS; chunk++) {
        uint32_t bo = (chunk & 1) ? STAGE_B : 0;
        if (chunk + 1 < KCHUNKS) {
            long long cs = (long long)(chunk + 1) * 64;
            uint32_t nbo = ((chunk + 1) & 1) ? STAGE_B : 0;
            cp16(sb + nbo + AH_OFF + d0, Ahc + so0 + cs);
            cp16(sb + nbo + AH_OFF + d1, Ahc + so1 + cs);
            cp16(sb + nbo + AL_OFF + d0, Alc + so0 + cs);
            cp16(sb + nbo + AL_OFF + d1, Alc + so1 + cs);
            cp16(sb + nbo + BH_OFF + d0, Bhc + so0 + cs);
            cp16(sb + nbo + BH_OFF + d1, Bhc + so1 + cs);
            cp16(sb + nbo + BL_OFF + d0, Blc + so0 + cs);
            cp16(sb + nbo + BL_OFF + d1, Blc + so1 + cs);
            cp_commit();
            cp_wait<1>();
        } else {
            cp_wait<0>();
        }
        __syncthreads();

#pragma unroll
        for (int ks = 0; ks < 2; ks++) {
            uint32_t kb = ks * 32;
            uint32_t ah[2][4], al[2][4];
#pragma unroll
            for (int i = 0; i < 2; i++) {
                ldsm4(ah[i][0], ah[i][1], ah[i][2], ah[i][3],
                      sb + bo + AH_OFF + aOff[i] + kb);
                ldsm4(al[i][0], al[i][1], al[i][2], al[i][3],
                      sb + bo + AL_OFF + aOff[i] + kb);
            }
            // per-jj B fragments, consumed immediately (low register pressure;
            // 4 independent accs between same-acc reuse)
#pragma unroll
            for (int jj = 0; jj < 4; jj++) {
                uint32_t h0, h1, h2, h3, l0, l1, l2, l3;
                ldsm4(h0, h1, h2, h3, sb + bo + BH_OFF + bOff[jj] + kb);
                ldsm4(l0, l1, l2, l3, sb + bo + BL_OFF + bOff[jj] + kb);
                int j0 = 2 * jj, j1 = 2 * jj + 1;
                // term ah*bh
                mma_bf16(acc[0][j0], ah[0], h0, h2);
                mma_bf16(acc[0][j1], ah[0], h1, h3);
                mma_bf16(acc[1][j0], ah[1], h0, h2);
                mma_bf16(acc[1][j1], ah[1], h1, h3);
                // term ah*bl
                mma_bf16(acc[0][j0], ah[0], l0, l2);
                mma_bf16(acc[0][j1], ah[0], l1, l3);
                mma_bf16(acc[1][j0], ah[1], l0, l2);
                mma_bf16(acc[1][j1], ah[1], l1, l3);
                // term al*bh
                mma_bf16(acc[0][j0], al[0], h0, h2);
                mma_bf16(acc[0][j1], al[0], h1, h3);
                mma_bf16(acc[1][j0], al[1], h0, h2);
                mma_bf16(acc[1][j1], al[1], h1, h3);
            }
        }
        __syncthreads();
    }

    float* Cz = g_ctx + (long long)z * GF * SS;
#pragma unroll
    for (int i = 0; i < 2; i++) {
        int f0 = mtile * 128 + m0w + i * 16 + (lane >> 2);
        float bias0 = bc[g * GF + f0];
        float bias1 = bc[g * GF + f0 + 8];
#pragma unroll
        for (int j = 0; j < 8; j++) {
            int s0 = stile * 128 + n0w + j * 8 + 2 * (lane & 3);
            if (s0 < SS) {
                float2 v0 = make_float2(acc[i][j][0] + bias0, acc[i][j][1] + bias0);
                float2 v1 = make_float2(acc[i][j][2] + bias1, acc[i][j][3] + bias1);
                *(float2*)(Cz + (long long)f0 * SS + s0) = v0;
                *(float2*)(Cz + (long long)(f0 + 8) * SS + s0) = v1;
            }
        }
    }
}

// ---------------- emb split-K partial GEMM ----------------------------------
__global__ void __launch_bounds__(256) emb_part_k(
    const float* __restrict__ A, const float* __restrict__ Bm)
{
    int z = blockIdx.z;
    int kbase = z * (IDIM / KSPLIT);

    __shared__ __align__(16) float As[32][33];
    __shared__ __align__(16) float Bs[32][65];

    int tid = threadIdx.x;
    int m0 = blockIdx.x * 32;
    int n0 = blockIdx.y * 64;
    int tx = tid % 64;
    int ty = tid / 64;

    float acc[8];
#pragma unroll
    for (int i = 0; i < 8; i++) acc[i] = 0.f;

    for (int k0 = kbase; k0 < kbase + IDIM / KSPLIT; k0 += 32) {
#pragma unroll
        for (int t = 0; t < 4; t++) {
            int lin = tid + 256 * t;
            int k = lin & 31, m = lin >> 5;
            As[k][m] = A[(m0 + m) * IDIM + k0 + k];
        }
#pragma unroll
        for (int t = 0; t < 8; t++) {
            int lin = tid + 256 * t;
            int k = lin & 31, n = lin >> 5;
            Bs[k][n] = Bm[(n0 + n) * IDIM + k0 + k];
        }
        __syncthreads();
#pragma unroll
        for (int k = 0; k < 32; k++) {
            float bv = Bs[k][tx];
#pragma unroll
            for (int i = 0; i < 8; i++)
                acc[i] += As[k][ty + 4 * i] * bv;
        }
        __syncthreads();
    }

    float* P = g_embP + (long long)z * TOT * NGR * GF;
#pragma unroll
    for (int i = 0; i < 8; i++) {
        int m = m0 + ty + 4 * i;
        P[m * (NGR * GF) + n0 + tx] = acc[i];
    }
}

__global__ void __launch_bounds__(256) emb_reduce_k(const float* __restrict__ ba) {
    int id = blockIdx.x * 256 + threadIdx.x;
    if (id >= TOT * NGR * GF) return;
    float v = ba[id & (NGR * GF - 1)];
#pragma unroll
    for (int z = 0; z < KSPLIT; z++)
        v += g_embP[z * (TOT * NGR * GF) + id];
    g_emb[id] = v;
}

// ---------------- generic GEMM (head): C = A * B^T, relu --------------------
__global__ void __launch_bounds__(256) gemm_nt_k(
    const float* __restrict__ A, int lda, long long aZ,
    const float* __restrict__ Bm, int ldb, long long bZ,
    const float* __restrict__ bias,
    float* __restrict__ C, int ldc, long long cZ,
    int K, int doRelu)
{
    int z = blockIdx.z;
    A  += (long long)z * aZ;
    Bm += (long long)z * bZ;
    C  += (long long)z * cZ;

    __shared__ __align__(16) float As[32][33];
    __shared__ __align__(16) float Bs[32][65];

    int tid = threadIdx.x;
    int m0 = blockIdx.x * 32;
    int n0 = blockIdx.y * 64;
    int tx = tid % 64;
    int ty = tid / 64;

    float acc[8];
#pragma unroll
    for (int i = 0; i < 8; i++) acc[i] = 0.f;

    for (int k0 = 0; k0 < K; k0 += 32) {
#pragma unroll
        for (int t = 0; t < 4; t++) {
            int lin = tid + 256 * t;
            int k = lin & 31, m = lin >> 5;
            As[k][m] = A[(m0 + m) * (long long)lda + k0 + k];
        }
#pragma unroll
        for (int t = 0; t < 8; t++) {
            int lin = tid + 256 * t;
            int k = lin & 31, n = lin >> 5;
            Bs[k][n] = Bm[(n0 + n) * (long long)ldb + k0 + k];
        }
        __syncthreads();
#pragma unroll
        for (int k = 0; k < 32; k++) {
            float bv = Bs[k][tx];
#pragma unroll
            for (int i = 0; i < 8; i++)
                acc[i] += As[k][ty + 4 * i] * bv;
        }
        __syncthreads();
    }

    float bb = bias ? bias[n0 + tx] : 0.f;
#pragma unroll
    for (int i = 0; i < 8; i++) {
        int m = m0 + ty + 4 * i;
        float v = acc[i] + bb;
        if (doRelu) v = fmaxf(v, 0.f);
        C[m * (long long)ldc + n0 + tx] = v;
    }
}

// ---------------- K3: adj logits (2 s-columns per thread) -------------------
__global__ void __launch_bounds__(256) adj_logits_k() {
    int g = blockIdx.y, b = blockIdx.z;
    __shared__ __align__(16) float a_s[GF * NMAX];   // [f][n]
    int tid = threadIdx.x;
    int cnt = g_cnt[b], off = g_off[b];

    for (int idx = tid; idx < GF * NMAX; idx += 256) {
        int n = idx >> 8, f = idx & 255;
        float v = 0.f;
        if (n < cnt) v = g_emb[(off + n) * (NGR * GF) + g * GF + f];
        a_s[f * NMAX + n] = v;
    }
    __syncthreads();

    int s0 = blockIdx.x * 512 + tid;
    int s1 = s0 + 256;
    if (s0 >= SS) return;
    bool ok1 = (s1 < SS);
    int s1c = ok1 ? s1 : s0;

    const float* ctxp = g_ctx + ((long long)(b * NGR + g)) * GF * SS;
    float acc0[NMAX], acc1[NMAX];
#pragma unroll
    for (int n = 0; n < NMAX; n++) { acc0[n] = 0.f; acc1[n] = 0.f; }

    const float4* ap = (const float4*)a_s;
#pragma unroll 2
    for (int f = 0; f < GF; f++) {
        float x0 = ctxp[(long long)f * SS + s0];
        float x1 = ctxp[(long long)f * SS + s1c];
        float4 a0 = ap[f * 4 + 0];
        float4 a1 = ap[f * 4 + 1];
        float4 a2 = ap[f * 4 + 2];
        float4 a3 = ap[f * 4 + 3];
        acc0[0]  += x0 * a0.x;  acc0[1]  += x0 * a0.y;  acc0[2]  += x0 * a0.z;  acc0[3]  += x0 * a0.w;
        acc0[4]  += x0 * a1.x;  acc0[5]  += x0 * a1.y;  acc0[6]  += x0 * a1.z;  acc0[7]  += x0 * a1.w;
        acc0[8]  += x0 * a2.x;  acc0[9]  += x0 * a2.y;  acc0[10] += x0 * a2.z;  acc0[11] += x0 * a2.w;
        acc0[12] += x0 * a3.x;  acc0[13] += x0 * a3.y;  acc0[14] += x0 * a3.z;  acc0[15] += x0 * a3.w;
        acc1[0]  += x1 * a0.x;  acc1[1]  += x1 * a0.y;  acc1[2]  += x1 * a0.z;  acc1[3]  += x1 * a0.w;
        acc1[4]  += x1 * a1.x;  acc1[5]  += x1 * a1.y;  acc1[6]  += x1 * a1.z;  acc1[7]  += x1 * a1.w;
        acc1[8]  += x1 * a2.x;  acc1[9]  += x1 * a2.y;  acc1[10] += x1 * a2.z;  acc1[11] += x1 * a2.w;
        acc1[12] += x1 * a3.x;  acc1[13] += x1 * a3.y;  acc1[14] += x1 * a3.z;  acc1[15] += x1 * a3.w;
    }

    float* adjp = g_adj + ((long long)(b * NGR + g)) * NMAX * SS;
#pragma unroll
    for (int n = 0; n < NMAX; n++) {
        adjp[(long long)n * SS + s0] = acc0[n];
        if (ok1) adjp[(long long)n * SS + s1] = acc1[n];
    }
}

// ---------------- K4: softmax -------------------------------------------------
__global__ void __launch_bounds__(256) softmax_k() {
    int n = blockIdx.x, g = blockIdx.y, b = blockIdx.z;
    if (n >= g_cnt[b]) return;
    float* row = g_adj + ((long long)((b * NGR + g) * NMAX + n)) * SS;
    int tid = threadIdx.x;
    __shared__ float red[8];

    float mx = -1e30f;
    for (int s = tid; s < SS; s += 256) mx = fmaxf(mx, row[s]);
#pragma unroll
    for (int o = 16; o > 0; o >>= 1) mx = fmaxf(mx, __shfl_xor_sync(0xffffffffu, mx, o));
    if ((tid & 31) == 0) red[tid >> 5] = mx;
    __syncthreads();
    if (tid < 32) {
        float v = (tid < 8) ? red[tid] : -1e30f;
#pragma unroll
        for (int o = 4; o > 0; o >>= 1) v = fmaxf(v, __shfl_xor_sync(0xffffffffu, v, o));
        if (tid == 0) red[0] = v;
    }
    __syncthreads();
    mx = red[0];
    __syncthreads();

    float sum = 0.f;
    for (int s = tid; s < SS; s += 256) {
        float e = __expf(row[s] - mx);
        row[s] = e;
        sum += e;
    }
#pragma unroll
    for (int o = 16; o > 0; o >>= 1) sum += __shfl_xor_sync(0xffffffffu, sum, o);
    if ((tid & 31) == 0) red[tid >> 5] = sum;
    __syncthreads();
    if (tid < 32) {
        float v = (tid < 8) ? red[tid] : 0.f;
#pragma unroll
        for (int o = 4; o > 0; o >>= 1) v += __shfl_xor_sync(0xffffffffu, v, o);
        if (tid == 0) red[0] = v;
    }
    __syncthreads();
    float inv = 1.f / red[0];
    for (int s = tid; s < SS; s += 256) row[s] *= inv;
}

// ---------------- K5: aggregate + residual -----------------------------------
__global__ void __launch_bounds__(256) aggregate_k() {
    int z = blockIdx.y;
    int b = z >> 2, g = z & 3;
    int f0 = blockIdx.x * 64;

    __shared__ __align__(16) float adjS[NMAX][33];
    __shared__ __align__(16) float ctxS[32][65];

    const float* adjp = g_adj + (long long)z * NMAX * SS;
    const float* ctxp = g_ctx + (long long)z * GF * SS;

    int tid = threadIdx.x;
    int fid = tid % 64, grp = tid / 64;
    float acc[4] = {0.f, 0.f, 0.f, 0.f};

    for (int s0 = 0; s0 < SS; s0 += 32) {
#pragma unroll
        for (int t = 0; t < 2; t++) {
            int lin = tid + 256 * t;
            int k = lin & 31, n = lin >> 5;
            adjS[n][k] = adjp[n * SS + s0 + k];
        }
#pragma unroll
        for (int t = 0; t < 8; t++) {
            int lin = tid + 256 * t;
            int k = lin & 31, i = lin >> 5;
            ctxS[k][i] = ctxp[(f0 + i) * SS + s0 + k];
        }
        __syncthreads();
#pragma unroll
        for (int k = 0; k < 32; k++) {
            float bv = ctxS[k][fid];
#pragma unroll
            for (int j = 0; j < 4; j++)
                acc[j] += adjS[grp * 4 + j][k] * bv;
        }
        __syncthreads();
    }

    int cnt = g_cnt[b], off = g_off[b];
#pragma unroll
    for (int j = 0; j < 4; j++) {
        int n = grp * 4 + j;
        if (n < cnt) {
            long long idx = (long long)(off + n) * (NGR * GF) + g * GF + f0 + fid;
            g_flat[idx] = acc[j] + g_emb[idx];
        }
    }
}

// ---------------- launch ----------------------------------------------------
extern "C" void kernel_launch(void* const* d_in, const int* in_sizes, int n_in,
                              void* d_out, int out_size) {
    const float* actor = (const float*)d_in[0];
    const float* fmap  = (const float*)d_in[1];
    const float* W_a   = (const float*)d_in[2];
    const float* b_a   = (const float*)d_in[3];
    const float* W_c   = (const float*)d_in[4];
    const float* b_c   = (const float*)d_in[5];
    const float* W_h   = (const float*)d_in[6];
    const void*  counts = d_in[7];
    int nbias = 0;
    for (int i = 0; i < n_in; i++) {
        switch (in_sizes[i]) {
            case TOT * IDIM:      actor = (const float*)d_in[i]; break;
            case NB * DIN * SS:   fmap  = (const float*)d_in[i]; break;
            case NGR * GF * IDIM: W_a   = (const float*)d_in[i]; break;
            case NGR * GF * DIN:  W_c   = (const float*)d_in[i]; break;
            case NGR * GF * GF:   W_h   = (const float*)d_in[i]; break;
            case NGR * GF:
                if (nbias++ == 0) b_a = (const float*)d_in[i];
                else              b_c = (const float*)d_in[i];
                break;
            case NB:              counts = d_in[i]; break;
            default: break;
        }
    }
    float* out = (float*)d_out;

    float* flat_p;
    cudaGetSymbolAddress((void**)&flat_p, g_flat);

    cudaFuncSetAttribute(ctx_mma_k, cudaFuncAttributeMaxDynamicSharedMemorySize,
                         SMEM_DYN);

    // ctx_mma_k placed at launch index 3 (empirically where ncu lands)
    init_offsets_k<<<1, 32>>>(counts);                                    // 0
    split_w_k<<<(NGR * GF * CPAD + 255) / 256, 256>>>(W_c);               // 1
    split_fm_k<<<dim3(SPAD / 32, CPAD / 32, NB), dim3(32, 8)>>>(fmap);    // 2
    ctx_mma_k<<<dim3(STILES * MTILES, NB * NGR), 256, SMEM_DYN>>>(b_c);   // 3
    emb_part_k<<<dim3(5, 16, KSPLIT), 256>>>(actor, W_a);                 // 4
    emb_reduce_k<<<(TOT * NGR * GF + 255) / 256, 256>>>(b_a);             // 5
    adj_logits_k<<<dim3(4, NGR, NB), 256>>>();                            // 6
    softmax_k<<<dim3(NMAX, NGR, NB), 256>>>();                            // 7
    aggregate_k<<<dim3(4, 64), 256>>>();                                  // 8
    gemm_nt_k<<<dim3(5, 4, 4), 256>>>(flat_p, NGR * GF, GF,               // 9
                                      W_h, GF, (long long)GF * GF,
                                      nullptr,
                                      out, NGR * GF, GF,
                                      GF, 1);
}